// round 3
// baseline (speedup 1.0000x reference)
#include <cuda_runtime.h>
#include <cstdint>

// Fixed problem maxima (from reference): 1M edges, 100K nodes, 2M pairs.
#define NE_MAX 1000000
#define NN_MAX 100000
#define CAP 16          // bucket capacity per edge (Poisson(2) degrees; fallback covers overflow)

// Scratch: allocation-free rule -> __device__ globals.
__device__ float g_P[(size_t)NE_MAX * 64];        // edge_attr @ W_edge[:, :64]^T
__device__ float g_Q[(size_t)NN_MAX * 64];        // [x|gs]    @ W_edge[:, 64:]^T
__device__ int   g_cnt[NE_MAX];                   // per-edge pair count
__device__ int   g_bkt[(size_t)NE_MAX * CAP];     // per-edge pair-id buckets

typedef unsigned long long u64;

__device__ __forceinline__ float eluf(float x) {
    return x > 0.f ? x : (__expf(x) - 1.f);
}
__device__ __forceinline__ u64 dup2(float v) {
    u64 r; asm("mov.b64 %0, {%1, %1};" : "=l"(r) : "f"(v)); return r;
}
__device__ __forceinline__ void fma2(u64& d, u64 a, u64 b) {
    asm("fma.rn.f32x2 %0, %1, %2, %0;" : "+l"(d) : "l"(a), "l"(b));
}
__device__ __forceinline__ float2 unpack2(u64 v) {
    float2 f; asm("mov.b64 {%0, %1}, %2;" : "=f"(f.x), "=f"(f.y) : "l"(v)); return f;
}

// ---------------------------------------------------------------------------
// K1: Q = xg @ W_edge[:, 64:106]^T   (M=NN, N=64, K=42) — tiled mini-GEMM.
// Block tile: 128 nodes x 64 cols, 256 threads, 4x8 register tile each.
// ---------------------------------------------------------------------------
__global__ __launch_bounds__(256) void node_proj_kernel(
    const float* __restrict__ x,
    const float* __restrict__ gs,
    const float* __restrict__ W_edge,
    int NN) {
    __shared__ float Xs[42][132];   // [k][node], padded
    __shared__ float Wn[42][64];    // [k][o]

    int tid = threadIdx.x;
    int n0  = blockIdx.x * 128;

    // Stage W (coalesced along the 42-wide row chunks)
    for (int s = tid; s < 64 * 42; s += 256) {
        int o = s / 42, i = s % 42;
        Wn[i][o] = W_edge[o * 106 + 64 + i];
    }
    // Stage x block (rows contiguous: 128*37 floats)
    for (int s = tid; s < 128 * 37; s += 256) {
        int nl = s / 37, i = s % 37;
        float v = (n0 + nl < NN) ? x[(size_t)n0 * 37 + s] : 0.f;
        Xs[i][nl] = v;
    }
    // Stage gs block (128*5 floats)
    for (int s = tid; s < 128 * 5; s += 256) {
        int nl = s / 5, j = s % 5;
        float v = (n0 + nl < NN) ? gs[(size_t)n0 * 5 + s] : 0.f;
        Xs[37 + j][nl] = v;
    }
    __syncthreads();

    int tr = tid >> 3;   // 0..31 -> node rows tr*4..+3
    int tc = tid & 7;    // 0..7  -> cols tc*8..+7

    float acc[4][8];
#pragma unroll
    for (int r = 0; r < 4; r++)
#pragma unroll
        for (int c = 0; c < 8; c++) acc[r][c] = 0.f;

#pragma unroll 6
    for (int k = 0; k < 42; k++) {
        float a[4], w[8];
        *(float4*)a       = *(const float4*)&Xs[k][tr * 4];
        *(float4*)w       = *(const float4*)&Wn[k][tc * 8];
        *(float4*)(w + 4) = *(const float4*)&Wn[k][tc * 8 + 4];
#pragma unroll
        for (int r = 0; r < 4; r++)
#pragma unroll
            for (int c = 0; c < 8; c++)
                acc[r][c] = fmaf(a[r], w[c], acc[r][c]);
    }

#pragma unroll
    for (int r = 0; r < 4; r++) {
        int n = n0 + tr * 4 + r;
        if (n < NN) {
            *(float4*)&g_Q[(size_t)n * 64 + tc * 8]     = *(float4*)&acc[r][0];
            *(float4*)&g_Q[(size_t)n * 64 + tc * 8 + 4] = *(float4*)&acc[r][4];
        }
    }
}

// ---------------------------------------------------------------------------
// K2: combined GEMM  [NE,64] x [64,128] with packed f32x2 FMA:
//   cols   0..63  -> out  = elu(E @ W_e^T + b_e)
//   cols  64..127 -> g_P  = E @ W_edge[:, :64]^T
// ---------------------------------------------------------------------------
#define SAS 132

__global__ __launch_bounds__(256, 2) void edge_gemm_kernel(
    const float* __restrict__ E,
    const float* __restrict__ W_edge,
    const float* __restrict__ W_e,
    const float* __restrict__ b_e,
    float* __restrict__ out,
    int NE) {
    extern __shared__ float sm[];
    float* As = sm;               // [64][SAS]  transposed A tile: As[k][row]
    float* Ws = sm + 64 * SAS;    // [64][128]  transposed weights: Ws[k][o]

    int tid = threadIdx.x;

    for (int s = tid; s < 64 * 128; s += 256) {
        int k = s >> 7, o = s & 127;
        float w = (o < 64) ? W_e[o * 64 + k] : W_edge[(o - 64) * 106 + k];
        Ws[k * 128 + o] = w;
    }

    int tr = tid >> 4;
    int tc = tid & 15;

    int ntiles = (NE + 127) >> 7;
    for (int t = blockIdx.x; t < ntiles; t += gridDim.x) {
        int row0 = t << 7;
        __syncthreads();

#pragma unroll
        for (int i = 0; i < 8; i++) {
            int s  = tid + i * 256;
            int r  = s >> 4, kq = s & 15;
            int row = row0 + r;
            float4 v = make_float4(0.f, 0.f, 0.f, 0.f);
            if (row < NE) v = *(const float4*)&E[(size_t)row * 64 + kq * 4];
            As[(kq * 4 + 0) * SAS + r] = v.x;
            As[(kq * 4 + 1) * SAS + r] = v.y;
            As[(kq * 4 + 2) * SAS + r] = v.z;
            As[(kq * 4 + 3) * SAS + r] = v.w;
        }
        __syncthreads();

        u64 acc2[32];
#pragma unroll
        for (int i = 0; i < 32; i++) acc2[i] = 0ull;

#pragma unroll 4
        for (int k = 0; k < 64; k++) {
            float a[8];
            *(float4*)(a)     = *(const float4*)&As[k * SAS + tr * 8];
            *(float4*)(a + 4) = *(const float4*)&As[k * SAS + tr * 8 + 4];
            ulonglong2 w01 = *(const ulonglong2*)&Ws[k * 128 + tc * 8];
            ulonglong2 w23 = *(const ulonglong2*)&Ws[k * 128 + tc * 8 + 4];
            u64 wp0 = w01.x, wp1 = w01.y, wp2 = w23.x, wp3 = w23.y;
#pragma unroll
            for (int i = 0; i < 8; i++) {
                u64 ad = dup2(a[i]);
                fma2(acc2[i * 4 + 0], ad, wp0);
                fma2(acc2[i * 4 + 1], ad, wp1);
                fma2(acc2[i * 4 + 2], ad, wp2);
                fma2(acc2[i * 4 + 3], ad, wp3);
            }
        }

        if (tc < 8) {
            float bb[8];
#pragma unroll
            for (int j = 0; j < 8; j++) bb[j] = __ldg(&b_e[tc * 8 + j]);
#pragma unroll
            for (int i = 0; i < 8; i++) {
                int row = row0 + tr * 8 + i;
                if (row < NE) {
                    float2 c0 = unpack2(acc2[i * 4 + 0]);
                    float2 c1 = unpack2(acc2[i * 4 + 1]);
                    float2 c2 = unpack2(acc2[i * 4 + 2]);
                    float2 c3 = unpack2(acc2[i * 4 + 3]);
                    float4 v0, v1;
                    v0.x = eluf(c0.x + bb[0]);
                    v0.y = eluf(c0.y + bb[1]);
                    v0.z = eluf(c1.x + bb[2]);
                    v0.w = eluf(c1.y + bb[3]);
                    v1.x = eluf(c2.x + bb[4]);
                    v1.y = eluf(c2.y + bb[5]);
                    v1.z = eluf(c3.x + bb[6]);
                    v1.w = eluf(c3.y + bb[7]);
                    *(float4*)&out[(size_t)row * 64 + tc * 8]     = v0;
                    *(float4*)&out[(size_t)row * 64 + tc * 8 + 4] = v1;
                }
            }
        } else {
            int c0 = tc * 8 - 64;
#pragma unroll
            for (int i = 0; i < 8; i++) {
                int row = row0 + tr * 8 + i;
                if (row < NE) {
                    ulonglong2 s0, s1;
                    s0.x = acc2[i * 4 + 0]; s0.y = acc2[i * 4 + 1];
                    s1.x = acc2[i * 4 + 2]; s1.y = acc2[i * 4 + 3];
                    *(ulonglong2*)&g_P[(size_t)row * 64 + c0]     = s0;
                    *(ulonglong2*)&g_P[(size_t)row * 64 + c0 + 4] = s1;
                }
            }
        }
    }
}

// ---------------------------------------------------------------------------
// K3a: zero the per-edge counters.
// ---------------------------------------------------------------------------
__global__ void zero_cnt_kernel(int NE) {
    int i = blockIdx.x * blockDim.x + threadIdx.x;
    if (i < NE) g_cnt[i] = 0;
}

// ---------------------------------------------------------------------------
// K3b: bucket pair ids by destination edge e0. Overflow (pos>=CAP, ~never)
// falls back to direct gather+elu+red so correctness holds for any input.
// ---------------------------------------------------------------------------
__global__ void fill_kernel(const float* __restrict__ b_edge,
                            const int* __restrict__ aidx,
                            const int* __restrict__ eidx,
                            float* __restrict__ out,
                            int NP) {
    int k = blockIdx.x * blockDim.x + threadIdx.x;
    if (k >= NP) return;
    int e0 = eidx[k];
    int pos = atomicAdd(&g_cnt[e0], 1);
    if (pos < CAP) {
        g_bkt[(size_t)e0 * CAP + pos] = k;
    } else {
        // cold fallback: do this pair's full row update directly
        int e1 = eidx[(size_t)NP + k];
        int a0 = aidx[k];
#pragma unroll
        for (int q = 0; q < 16; q++) {
            float4 p  = *(const float4*)&g_P[(size_t)e1 * 64 + q * 4];
            float4 qv = *(const float4*)&g_Q[(size_t)a0 * 64 + q * 4];
            float h0 = eluf(p.x + qv.x + b_edge[q * 4 + 0]);
            float h1 = eluf(p.y + qv.y + b_edge[q * 4 + 1]);
            float h2 = eluf(p.z + qv.z + b_edge[q * 4 + 2]);
            float h3 = eluf(p.w + qv.w + b_edge[q * 4 + 3]);
            float* addr = out + (size_t)e0 * 64 + q * 4;
            asm volatile("red.global.add.v4.f32 [%0], {%1,%2,%3,%4};"
                         :: "l"(addr), "f"(h0), "f"(h1), "f"(h2), "f"(h3)
                         : "memory");
        }
    }
}

// ---------------------------------------------------------------------------
// K3c: per-edge gather-reduce. 16 threads own one out row; no float atomics.
// ---------------------------------------------------------------------------
__global__ __launch_bounds__(256) void edge_reduce_kernel(
    const float* __restrict__ b_edge,
    const int* __restrict__ aidx,
    const int* __restrict__ eidx,
    float* __restrict__ out,
    int NP, int NE) {
    __shared__ float bs[64];
    int tid = threadIdx.x;
    if (tid < 64) bs[tid] = b_edge[tid];
    __syncthreads();

    int e = blockIdx.x * 16 + (tid >> 4);
    int q = tid & 15;
    if (e >= NE) return;

    int deg = g_cnt[e];
    if (deg == 0) return;
    int n = min(deg, CAP);

    float4 b4 = *(float4*)&bs[q * 4];
    float4 acc = make_float4(0.f, 0.f, 0.f, 0.f);

    for (int i = 0; i < n; i++) {
        int pid = g_bkt[(size_t)e * CAP + i];
        int e1  = __ldg(&eidx[(size_t)NP + pid]);
        int a0  = __ldg(&aidx[pid]);
        float4 p  = __ldg((const float4*)&g_P[(size_t)e1 * 64 + q * 4]);
        float4 qv = __ldg((const float4*)&g_Q[(size_t)a0 * 64 + q * 4]);
        acc.x += eluf(p.x + qv.x + b4.x);
        acc.y += eluf(p.y + qv.y + b4.y);
        acc.z += eluf(p.z + qv.z + b4.z);
        acc.w += eluf(p.w + qv.w + b4.w);
    }

    float4* o = (float4*)&out[(size_t)e * 64 + q * 4];
    float4 v = *o;
    v.x += acc.x; v.y += acc.y; v.z += acc.z; v.w += acc.w;
    *o = v;
}

// ---------------------------------------------------------------------------
extern "C" void kernel_launch(void* const* d_in, const int* in_sizes, int n_in,
                              void* d_out, int out_size) {
    const float* x      = (const float*)d_in[0];
    const float* gs     = (const float*)d_in[1];
    const float* E      = (const float*)d_in[2];
    const float* W_edge = (const float*)d_in[3];
    const float* b_edge = (const float*)d_in[4];
    const float* W_e    = (const float*)d_in[5];
    const float* b_e    = (const float*)d_in[6];
    const int*   aidx   = (const int*)d_in[7];
    const int*   eidx   = (const int*)d_in[8];
    float* out = (float*)d_out;

    int NN = in_sizes[0] / 37;
    int NE = in_sizes[2] / 64;
    int NP = in_sizes[7] / 2;
    if (NN > NN_MAX) NN = NN_MAX;
    if (NE > NE_MAX) NE = NE_MAX;

    // K1: node projections -> g_Q
    node_proj_kernel<<<(NN + 127) / 128, 256>>>(x, gs, W_edge, NN);

    // K2: fused edge GEMM -> out (elu half) + g_P
    const int smem_bytes = (64 * SAS + 64 * 128) * (int)sizeof(float);  // 66560
    cudaFuncSetAttribute(edge_gemm_kernel,
                         cudaFuncAttributeMaxDynamicSharedMemorySize, smem_bytes);
    edge_gemm_kernel<<<296, 256, smem_bytes>>>(E, W_edge, W_e, b_e, out, NE);

    // K3: atomic-free scatter via bucketing
    zero_cnt_kernel<<<(NE + 1023) / 1024, 1024>>>(NE);
    fill_kernel<<<(NP + 255) / 256, 256>>>(b_edge, aidx, eidx, out, NP);
    edge_reduce_kernel<<<(NE + 15) / 16, 256>>>(b_edge, aidx, eidx, out, NP, NE);
}